// round 17
// baseline (speedup 1.0000x reference)
#include <cuda_runtime.h>
#include <cuda_fp16.h>
#include <math.h>

#define DIMX 1024
#define NH   16
#define HD   64
#define DFF  4096
#define BB   2
#define SSQ  2048
#define MTOT (BB*SSQ)
#define EPSV 1e-6f
#define PGRID 296   /* 148 SMs x 2 CTAs */

// ---------------- scratch (device globals) ----------------------------------
__device__ __align__(256) __half g_h   [MTOT*DIMX];
__device__ __align__(256) __half g_q   [MTOT*DIMX];
__device__ __align__(256) __half g_k   [MTOT*DIMX];
__device__ __align__(256) __half g_v   [MTOT*DIMX];   // vT [1024][MTOT]
__device__ __align__(256) __half g_attn[MTOT*DIMX];
__device__ __align__(256) float  g_x2  [MTOT*DIMX];
__device__ __align__(256) __half g_ffh [MTOT*DFF];
__device__ __align__(256) __half g_wt  [12*1024*1024];  // transposed fp16 weights

// ---------------- helpers ----------------------------------------------------
__device__ __forceinline__ void cp16(unsigned s, const void* g) {
    asm volatile("cp.async.cg.shared.global [%0], [%1], 16;" :: "r"(s), "l"(g));
}
#define CP_COMMIT() asm volatile("cp.async.commit_group;")
#define CP_WAIT(n)  asm volatile("cp.async.wait_group %0;" :: "n"(n))

#define MMA_F16(c, a0, a1, a2, a3, b0, b1) asm volatile( \
    "mma.sync.aligned.m16n8k16.row.col.f32.f16.f16.f32 " \
    "{%0,%1,%2,%3}, {%4,%5,%6,%7}, {%8,%9}, {%0,%1,%2,%3};" \
    : "+f"((c)[0]), "+f"((c)[1]), "+f"((c)[2]), "+f"((c)[3]) \
    : "r"(a0), "r"(a1), "r"(a2), "r"(a3), "r"(b0), "r"(b1))

#define LDSM4(r, a) asm volatile( \
    "ldmatrix.sync.aligned.m8n8.x4.shared.b16 {%0,%1,%2,%3}, [%4];" \
    : "=r"((r)[0]), "=r"((r)[1]), "=r"((r)[2]), "=r"((r)[3]) : "r"(a))

__device__ __forceinline__ unsigned packh2(float a, float b) {
    unsigned u;
    asm("cvt.rn.f16x2.f32 %0, %2, %1;" : "=r"(u) : "f"(a), "f"(b));
    return u;
}
__device__ __forceinline__ unsigned ex2h2(unsigned a) {
    unsigned u;
    asm("ex2.approx.f16x2 %0, %1;" : "=r"(u) : "r"(a));
    return u;
}

// ---------------- merged weight prep (single launch) --------------------------
__global__ void __launch_bounds__(256) prep_all_T(
    const float* __restrict__ wq, const float* __restrict__ wk,
    const float* __restrict__ wv, const float* __restrict__ wo,
    const float* __restrict__ wu, const float* __restrict__ wd,
    __half* __restrict__ wt)
{
    __shared__ float t[32][33];
    int bid = blockIdx.x;
    const float* w; __half* o; int K, N, tile;
    if      (bid < 1024) { w = wq; o = wt;                 K = 1024; N = 1024; tile = bid; }
    else if (bid < 2048) { w = wk; o = wt + 1*1024*1024;   K = 1024; N = 1024; tile = bid - 1024; }
    else if (bid < 3072) { w = wv; o = wt + 2*1024*1024;   K = 1024; N = 1024; tile = bid - 2048; }
    else if (bid < 4096) { w = wo; o = wt + 3*1024*1024;   K = 1024; N = 1024; tile = bid - 3072; }
    else if (bid < 8192) { w = wu; o = wt + 4*1024*1024;   K = 1024; N = 4096; tile = bid - 4096; }
    else                 { w = wd; o = wt + 8*1024*1024;   K = 4096; N = 1024; tile = bid - 8192; }
    int ntN = N >> 5;
    int nb = (tile % ntN) << 5;
    int kt = (tile / ntN) << 5;
    int tid = threadIdx.x;
    #pragma unroll
    for (int i = 0; i < 4; i++) {
        int idx = tid + (i << 8);
        int r = idx >> 5, c = idx & 31;
        t[r][c] = w[(size_t)(kt + r) * N + nb + c];
    }
    __syncthreads();
    #pragma unroll
    for (int i = 0; i < 4; i++) {
        int idx = tid + (i << 8);
        int r = idx >> 5, c = idx & 31;
        o[(size_t)(nb + r) * K + kt + c] = __float2half(t[c][r]);
    }
}

// ---------------- LayerNorm (emits fp16) --------------------------------------
__global__ void __launch_bounds__(256) ln_kernel(
    const float* __restrict__ x, const float* __restrict__ alpha,
    const float* __restrict__ beta, __half* __restrict__ y)
{
    int row = blockIdx.x;
    int t = threadIdx.x;
    const float4* xr = reinterpret_cast<const float4*>(x + (size_t)row * DIMX);
    float4 v = xr[t];
    float s  = v.x + v.y + v.z + v.w;
    float sq = v.x*v.x + v.y*v.y + v.z*v.z + v.w*v.w;
    #pragma unroll
    for (int o = 16; o; o >>= 1) {
        s  += __shfl_xor_sync(0xffffffffu, s,  o);
        sq += __shfl_xor_sync(0xffffffffu, sq, o);
    }
    __shared__ float ss[8], ssq[8];
    int w = t >> 5, l = t & 31;
    if (l == 0) { ss[w] = s; ssq[w] = sq; }
    __syncthreads();
    if (w == 0) {
        s  = (l < 8) ? ss[l]  : 0.f;
        sq = (l < 8) ? ssq[l] : 0.f;
        #pragma unroll
        for (int o = 4; o; o >>= 1) {
            s  += __shfl_xor_sync(0xffffffffu, s,  o);
            sq += __shfl_xor_sync(0xffffffffu, sq, o);
        }
        if (l == 0) { ss[0] = s; ssq[0] = sq; }
    }
    __syncthreads();
    s = ss[0]; sq = ssq[0];
    float mu  = s * (1.0f / DIMX);
    float var = (sq - (float)DIMX * mu * mu) * (1.0f / (DIMX - 1));
    float sig = sqrtf(fmaxf(var, 0.f));
    float inv = 1.0f / (sig + EPSV);
    float4 a = reinterpret_cast<const float4*>(alpha)[t];
    float4 b = reinterpret_cast<const float4*>(beta)[t];
    __half2 h0 = __floats2half2_rn(a.x * (v.x - mu) * inv + b.x,
                                   a.y * (v.y - mu) * inv + b.y);
    __half2 h1 = __floats2half2_rn(a.z * (v.z - mu) * inv + b.z,
                                   a.w * (v.w - mu) * inv + b.w);
    size_t off = (size_t)row * DIMX + t * 4;
    reinterpret_cast<__half2*>(y + off)[0] = h0;
    reinterpret_cast<__half2*>(y + off)[1] = h1;
}

// ---------------- FP16 tensor GEMM: persistent tiles ---------------------------
// OM: 0 = fp32 out (+res), 2 = fp16 rows, 4 = fused QKV (q scaled 1/8, k rows,
// v transposed).
#define STAGES 4
#define PW 20
#define STAGE_U32 (256*PW)
#define GEMM_SMEM (STAGES * STAGE_U32 * 4)

template<int OM, bool BIAS, bool RELU, bool RES>
__global__ void __launch_bounds__(256, 2) gemm_fp16(
    const __half* __restrict__ A, const __half* __restrict__ Bt,
    const float* __restrict__ bias, const float* __restrict__ res,
    float* __restrict__ C, __half* __restrict__ Ch,
    __half* __restrict__ Ch2, __half* __restrict__ Ch3,
    int M, int N, int K)
{
    extern __shared__ unsigned smg[];
    const int tid  = threadIdx.x;
    const int warp = tid >> 5, lane = tid & 31;
    const int wm   = (warp >> 2) << 6;
    const int wn   = (warp & 3) << 5;
    const int g    = lane >> 2, q = lane & 3;
    const int lr   = (lane & 7) + ((lane >> 3) & 1) * 8;
    const int lc   = (lane >> 4) * 4;

    const unsigned sbase = (unsigned)__cvta_generic_to_shared(smg);
    const int nt = K >> 5;
    const int ntx = N >> 7;
    const int ntiles = ntx * (M >> 7);

    #define G_ISSUE(buf, kt) do { \
        unsigned ab_ = sbase + (buf) * (STAGE_U32 * 4); \
        unsigned bb_ = ab_ + 128 * PW * 4; \
        _Pragma("unroll") \
        for (int i_ = 0; i_ < 2; i_++) { \
            int idx_ = tid + (i_ << 8); \
            int row_ = idx_ >> 2, seg_ = idx_ & 3; \
            cp16(ab_ + (row_ * PW + seg_ * 4) * 4, \
                 A  + (size_t)(bm + row_) * K + (kt) * 32 + seg_ * 8); \
            cp16(bb_ + (row_ * PW + seg_ * 4) * 4, \
                 Bt + (size_t)(bn + row_) * K + (kt) * 32 + seg_ * 8); \
        } \
    } while (0)

    for (int tile = blockIdx.x; tile < ntiles; tile += gridDim.x) {
        const int bm = (tile / ntx) << 7;
        const int bn = (tile % ntx) << 7;

        float acc[4][4][4];
        #pragma unroll
        for (int mi = 0; mi < 4; mi++)
            #pragma unroll
            for (int nj = 0; nj < 4; nj++)
                #pragma unroll
                for (int e = 0; e < 4; e++) acc[mi][nj][e] = 0.f;

        #pragma unroll
        for (int s = 0; s < STAGES - 1; s++) {
            if (s < nt) G_ISSUE(s, s);
            CP_COMMIT();
        }

        for (int kt = 0; kt < nt; kt++) {
            CP_WAIT(STAGES - 2);
            __syncthreads();
            int nl = kt + STAGES - 1;
            if (nl < nt) G_ISSUE(nl % STAGES, nl);
            CP_COMMIT();

            const unsigned ab = sbase + (kt % STAGES) * (STAGE_U32 * 4);
            const unsigned bb = ab + 128 * PW * 4;
            #pragma unroll
            for (int ks = 0; ks < 2; ks++) {
                const int kw = ks << 3;
                unsigned af[4][4], bp[2][4];
                #pragma unroll
                for (int mi = 0; mi < 4; mi++)
                    LDSM4(af[mi], ab + (((wm + (mi << 4) + lr) * PW) + kw + lc) * 4);
                #pragma unroll
                for (int p = 0; p < 2; p++)
                    LDSM4(bp[p], bb + (((wn + (p << 4) + lr) * PW) + kw + lc) * 4);
                #pragma unroll
                for (int mi = 0; mi < 4; mi++)
                    #pragma unroll
                    for (int nj = 0; nj < 4; nj++)
                        MMA_F16(acc[mi][nj], af[mi][0], af[mi][1], af[mi][2], af[mi][3],
                                bp[nj >> 1][nj & 1], bp[nj >> 1][2 + (nj & 1)]);
            }
        }

        // epilogue
        #pragma unroll
        for (int mi = 0; mi < 4; mi++) {
            int r = bm + wm + (mi << 4) + g;
            #pragma unroll
            for (int nj = 0; nj < 4; nj++) {
                int c = bn + wn + (nj << 3) + (q << 1);
                float2 v0, v1;
                v0.x = acc[mi][nj][0]; v0.y = acc[mi][nj][1];
                v1.x = acc[mi][nj][2]; v1.y = acc[mi][nj][3];
                if (BIAS) {
                    float2 bv = *reinterpret_cast<const float2*>(bias + c);
                    v0.x += bv.x; v0.y += bv.y; v1.x += bv.x; v1.y += bv.y;
                }
                if (RELU) {
                    v0.x = fmaxf(v0.x, 0.f); v0.y = fmaxf(v0.y, 0.f);
                    v1.x = fmaxf(v1.x, 0.f); v1.y = fmaxf(v1.y, 0.f);
                }
                if (RES) {
                    float2 r0 = *reinterpret_cast<const float2*>(res + (size_t)r * N + c);
                    float2 r1 = *reinterpret_cast<const float2*>(res + (size_t)(r + 8) * N + c);
                    v0.x += r0.x; v0.y += r0.y; v1.x += r1.x; v1.y += r1.y;
                }
                if (OM == 0) {
                    *reinterpret_cast<float2*>(C + (size_t)r * N + c) = v0;
                    *reinterpret_cast<float2*>(C + (size_t)(r + 8) * N + c) = v1;
                } else if (OM == 2) {
                    *reinterpret_cast<__half2*>(Ch + (size_t)r * N + c) = __floats2half2_rn(v0.x, v0.y);
                    *reinterpret_cast<__half2*>(Ch + (size_t)(r + 8) * N + c) = __floats2half2_rn(v1.x, v1.y);
                } else {  // OM == 4: fused QKV
                    if (bn < 1024) {
                        *reinterpret_cast<__half2*>(Ch + (size_t)r * DIMX + c) =
                            __floats2half2_rn(v0.x * 0.125f, v0.y * 0.125f);
                        *reinterpret_cast<__half2*>(Ch + (size_t)(r + 8) * DIMX + c) =
                            __floats2half2_rn(v1.x * 0.125f, v1.y * 0.125f);
                    } else if (bn < 2048) {
                        int ck = c - 1024;
                        *reinterpret_cast<__half2*>(Ch2 + (size_t)r * DIMX + ck) = __floats2half2_rn(v0.x, v0.y);
                        *reinterpret_cast<__half2*>(Ch2 + (size_t)(r + 8) * DIMX + ck) = __floats2half2_rn(v1.x, v1.y);
                    } else {
                        int cv = c - 2048;
                        Ch3[(size_t)cv * M + r]           = __float2half(v0.x);
                        Ch3[(size_t)(cv + 1) * M + r]     = __float2half(v0.y);
                        Ch3[(size_t)cv * M + r + 8]       = __float2half(v1.x);
                        Ch3[(size_t)(cv + 1) * M + r + 8] = __float2half(v1.y);
                    }
                }
            }
        }
        __syncthreads();   // all reads of smem done before next tile's issues
    }
    #undef G_ISSUE
}

// ---------------- FP16 flash attention (rd15 + corr-skip) ---------------------
#define QST 36
#define ATT_SMEM ((128*QST + 2*64*QST + 2*64*QST) * 4)

__global__ void __launch_bounds__(256, 2) attn_tc(
    const __half* __restrict__ qb, const __half* __restrict__ kb,
    const __half* __restrict__ vT, __half* __restrict__ og)
{
    extern __shared__ unsigned sma[];
    unsigned* Qs = sma;

    const int tid  = threadIdx.x;
    const int warp = tid >> 5, lane = tid & 31;
    const int g    = lane >> 2, q4 = lane & 3;
    const int lr   = (lane & 7) + ((lane >> 3) & 1) * 8;
    const int lc   = (lane >> 4) * 4;
    const int bh   = blockIdx.y;
    const int b    = bh >> 4, h = bh & 15;
    const int q0   = blockIdx.x * 128;
    const size_t rbase = (size_t)b * SSQ;
    const int r0 = warp << 4;
    const unsigned sbase = (unsigned)__cvta_generic_to_shared(sma);
    const unsigned ksb = sbase + 128 * QST * 4;
    const unsigned vsb = ksb + 2 * 64 * QST * 4;

    #pragma unroll
    for (int i = 0; i < 4; i++) {
        int f = tid + (i << 8);
        int row = f >> 3, seg = f & 7;
        cp16(sbase + (row * QST + seg * 4) * 4,
             qb + ((rbase + q0 + row) << 10) + (h << 6) + (seg << 3));
    }
    CP_COMMIT();

    #define A_ISSUE(buf, kt) do { \
        _Pragma("unroll") \
        for (int i_ = 0; i_ < 2; i_++) { \
            int f_ = tid + (i_ << 8); \
            int rr_ = f_ >> 3, sg_ = f_ & 7; \
            cp16(ksb + ((buf) * 64 * QST + rr_ * QST + sg_ * 4) * 4, \
                 kb + ((rbase + (kt) + rr_) << 10) + (h << 6) + (sg_ << 3)); \
            cp16(vsb + ((buf) * 64 * QST + rr_ * QST + sg_ * 4) * 4, \
                 vT + (size_t)((h << 6) + rr_) * MTOT + rbase + (kt) + (sg_ << 3)); \
        } \
    } while (0)

    CP_WAIT(0);
    __syncthreads();
    unsigned aq[4][4];
    #pragma unroll
    for (int ks = 0; ks < 4; ks++) {
        aq[ks][0] = Qs[(r0 + g) * QST + (ks << 3) + q4];
        aq[ks][1] = Qs[(r0 + 8 + g) * QST + (ks << 3) + q4];
        aq[ks][2] = Qs[(r0 + g) * QST + (ks << 3) + q4 + 4];
        aq[ks][3] = Qs[(r0 + 8 + g) * QST + (ks << 3) + q4 + 4];
    }

    A_ISSUE(0, 0);
    CP_COMMIT();

    float m0 = -1e30f, m1 = -1e30f, l0 = 0.f, l1 = 0.f;
    float oacc[8][4];
    #pragma unroll
    for (int j = 0; j < 8; j++)
        #pragma unroll
        for (int e = 0; e < 4; e++) oacc[j][e] = 0.f;

    const float L2E = 1.4426950408889634f;
    const int NKT = SSQ / 64;
    for (int t = 0; t < NKT; t++) {
        __syncthreads();
        if (t + 1 < NKT) A_ISSUE((t + 1) & 1, (t + 1) * 64);
        CP_COMMIT();
        CP_WAIT(1);
        __syncthreads();

        const unsigned kbb = ksb + (t & 1) * 64 * QST * 4;
        const unsigned vbb = vsb + (t & 1) * 64 * QST * 4;

        float s[8][4];
        #pragma unroll
        for (int j = 0; j < 8; j++)
            #pragma unroll
            for (int e = 0; e < 4; e++) s[j][e] = 0.f;
        #pragma unroll
        for (int ks = 0; ks < 4; ks++) {
            const int kw = ks << 3;
            #pragma unroll
            for (int p = 0; p < 4; p++) {
                unsigned bk[4];
                LDSM4(bk, kbb + ((((p << 4) + lr) * QST) + kw + lc) * 4);
                MMA_F16(s[2*p],     aq[ks][0], aq[ks][1], aq[ks][2], aq[ks][3], bk[0], bk[2]);
                MMA_F16(s[2*p + 1], aq[ks][0], aq[ks][1], aq[ks][2], aq[ks][3], bk[1], bk[3]);
            }
        }

        float mt0 = -1e30f, mt1 = -1e30f;
        #pragma unroll
        for (int j = 0; j < 8; j++) {
            mt0 = fmaxf(mt0, fmaxf(s[j][0], s[j][1]));
            mt1 = fmaxf(mt1, fmaxf(s[j][2], s[j][3]));
        }
        mt0 = fmaxf(mt0, __shfl_xor_sync(0xffffffffu, mt0, 1));
        mt0 = fmaxf(mt0, __shfl_xor_sync(0xffffffffu, mt0, 2));
        mt1 = fmaxf(mt1, __shfl_xor_sync(0xffffffffu, mt1, 1));
        mt1 = fmaxf(mt1, __shfl_xor_sync(0xffffffffu, mt1, 2));
        float mn0 = fmaxf(m0, mt0), mn1 = fmaxf(m1, mt1);
        float corr0 = __expf(m0 - mn0), corr1 = __expf(m1 - mn1);
        m0 = mn0; m1 = mn1;
        float b0l = mn0 * L2E, b1l = mn1 * L2E;

        unsigned p01[8], p23[8];
        __half2 acc0 = __floats2half2_rn(0.f, 0.f);
        __half2 acc1 = acc0;
        #pragma unroll
        for (int j = 0; j < 8; j++) {
            unsigned u01 = packh2(fmaf(s[j][0], L2E, -b0l), fmaf(s[j][1], L2E, -b0l));
            unsigned u23 = packh2(fmaf(s[j][2], L2E, -b1l), fmaf(s[j][3], L2E, -b1l));
            p01[j] = ex2h2(u01);
            p23[j] = ex2h2(u23);
            acc0 = __hadd2(acc0, *reinterpret_cast<__half2*>(&p01[j]));
            acc1 = __hadd2(acc1, *reinterpret_cast<__half2*>(&p23[j]));
        }
        float ls0 = __low2float(acc0) + __high2float(acc0);
        float ls1 = __low2float(acc1) + __high2float(acc1);
        ls0 += __shfl_xor_sync(0xffffffffu, ls0, 1);
        ls0 += __shfl_xor_sync(0xffffffffu, ls0, 2);
        ls1 += __shfl_xor_sync(0xffffffffu, ls1, 1);
        ls1 += __shfl_xor_sync(0xffffffffu, ls1, 2);
        l0 = l0 * corr0 + ls0;
        l1 = l1 * corr1 + ls1;

        // skip oacc rescale when max unchanged for whole warp (corr == 1.0 exactly)
        if (!__all_sync(0xffffffffu, (corr0 == 1.0f) && (corr1 == 1.0f))) {
            #pragma unroll
            for (int j = 0; j < 8; j++) {
                oacc[j][0] *= corr0; oacc[j][1] *= corr0;
                oacc[j][2] *= corr1; oacc[j][3] *= corr1;
            }
        }

        #pragma unroll
        for (int ks = 0; ks < 4; ks++) {
            const int kw = ks << 3;
            unsigned ap0 = p01[2*ks],     ap1 = p23[2*ks];
            unsigned ap2 = p01[2*ks + 1], ap3 = p23[2*ks + 1];
            #pragma unroll
            for (int p = 0; p < 4; p++) {
                unsigned bv[4];
                LDSM4(bv, vbb + ((((p << 4) + lr) * QST) + kw + lc) * 4);
                MMA_F16(oacc[2*p],     ap0, ap1, ap2, ap3, bv[0], bv[2]);
                MMA_F16(oacc[2*p + 1], ap0, ap1, ap2, ap3, bv[1], bv[3]);
            }
        }
    }

    const size_t obase = rbase * DIMX + (size_t)h * HD;
    float il0 = 1.0f / l0, il1 = 1.0f / l1;
    #pragma unroll
    for (int j = 0; j < 8; j++) {
        size_t o0 = obase + (size_t)(q0 + r0 + g) * DIMX + (j << 3) + (q4 << 1);
        size_t o1 = obase + (size_t)(q0 + r0 + 8 + g) * DIMX + (j << 3) + (q4 << 1);
        *reinterpret_cast<__half2*>(og + o0) =
            __floats2half2_rn(oacc[j][0] * il0, oacc[j][1] * il0);
        *reinterpret_cast<__half2*>(og + o1) =
            __floats2half2_rn(oacc[j][2] * il1, oacc[j][3] * il1);
    }
}

// ---------------- launch ------------------------------------------------------
extern "C" void kernel_launch(void* const* d_in, const int* in_sizes, int n_in,
                              void* d_out, int out_size)
{
    const float* x    = (const float*)d_in[0];
    const float* wq   = (const float*)d_in[2];
    const float* wk   = (const float*)d_in[3];
    const float* wv   = (const float*)d_in[4];
    const float* wo   = (const float*)d_in[5];
    const float* w_up = (const float*)d_in[6];
    const float* b_up = (const float*)d_in[7];
    const float* w_dn = (const float*)d_in[8];
    const float* b_dn = (const float*)d_in[9];
    const float* l1a  = (const float*)d_in[10];
    const float* l1b  = (const float*)d_in[11];
    const float* l2a  = (const float*)d_in[12];
    const float* l2b  = (const float*)d_in[13];
    float* out = (float*)d_out;

    __half *h, *qb, *kb, *vT, *attn, *ffh, *wt;
    float *x2;
    {
        void* p;
        cudaGetSymbolAddress(&p, g_h);    h    = (__half*)p;
        cudaGetSymbolAddress(&p, g_q);    qb   = (__half*)p;
        cudaGetSymbolAddress(&p, g_k);    kb   = (__half*)p;
        cudaGetSymbolAddress(&p, g_v);    vT   = (__half*)p;
        cudaGetSymbolAddress(&p, g_attn); attn = (__half*)p;
        cudaGetSymbolAddress(&p, g_x2);   x2   = (float*)p;
        cudaGetSymbolAddress(&p, g_ffh);  ffh  = (__half*)p;
        cudaGetSymbolAddress(&p, g_wt);   wt   = (__half*)p;
    }

    __half* wqkv_t = wt;
    __half* wo_t   = wt + 3 * 1024 * 1024;
    __half* wu_t   = wt + 4 * 1024 * 1024;
    __half* wd_t   = wt + 8 * 1024 * 1024;

    cudaFuncSetAttribute(gemm_fp16<4,false,false,false>, cudaFuncAttributeMaxDynamicSharedMemorySize, GEMM_SMEM);
    cudaFuncSetAttribute(gemm_fp16<0,false,false,true >, cudaFuncAttributeMaxDynamicSharedMemorySize, GEMM_SMEM);
    cudaFuncSetAttribute(gemm_fp16<2,true ,true ,false>, cudaFuncAttributeMaxDynamicSharedMemorySize, GEMM_SMEM);
    cudaFuncSetAttribute(gemm_fp16<0,true ,false,true >, cudaFuncAttributeMaxDynamicSharedMemorySize, GEMM_SMEM);
    cudaFuncSetAttribute(attn_tc, cudaFuncAttributeMaxDynamicSharedMemorySize, ATT_SMEM);

    dim3 thr(256);

    prep_all_T<<<12288, thr>>>(wq, wk, wv, wo, w_up, w_dn, wt);

    ln_kernel<<<MTOT, thr>>>(x, l1a, l1b, h);

    gemm_fp16<4,false,false,false><<<PGRID, thr, GEMM_SMEM>>>(
        h, wqkv_t, nullptr, nullptr, nullptr, qb, kb, vT, MTOT, 3072, DIMX);

    attn_tc<<<dim3(SSQ/128, BB*NH), thr, ATT_SMEM>>>(qb, kb, vT, attn);

    gemm_fp16<0,false,false,true><<<PGRID, thr, GEMM_SMEM>>>(
        attn, wo_t, nullptr, x, x2, nullptr, nullptr, nullptr, MTOT, DIMX, DIMX);

    ln_kernel<<<MTOT, thr>>>(x2, l2a, l2b, h);

    gemm_fp16<2,true,true,false><<<PGRID, thr, GEMM_SMEM>>>(
        h, wu_t, b_up, nullptr, nullptr, ffh, nullptr, nullptr, MTOT, DFF, DIMX);

    gemm_fp16<0,true,false,true><<<PGRID, thr, GEMM_SMEM>>>(
        ffh, wd_t, b_dn, x2, out, nullptr, nullptr, nullptr, MTOT, DIMX, DFF);
}